// round 2
// baseline (speedup 1.0000x reference)
#include <cuda_runtime.h>
#include <cuda_bf16.h>

#define NA 8192
#define NP 65536
#define FDIM 128
#define RD 20
#define NB 5
#define TM 16

// Scratch (allocation-free rule: __device__ globals)
__device__ __align__(16) float g_x[NA * 384];
__device__ __align__(16) float g_dq[NA * FDIM];
__device__ __align__(16) float g_dmu[NA * 384];

__device__ __forceinline__ float silu(float z) { return z / (1.f + __expf(-z)); }

__device__ __forceinline__ void red4(float* p, float a, float b, float c, float d) {
    asm volatile("red.global.add.v4.f32 [%0], {%1,%2,%3,%4};"
                 :: "l"(p), "f"(a), "f"(b), "f"(c), "f"(d) : "memory");
}

// ---------------------------------------------------------------------------
// Kernel 1: x = silu(q @ W1 + b1) @ W2 + b2     (per-atom, TM atoms per CTA)
// ---------------------------------------------------------------------------
__global__ void __launch_bounds__(128) k_x(
    const float* __restrict__ q,
    const float* __restrict__ W1, const float* __restrict__ b1,
    const float* __restrict__ W2, const float* __restrict__ b2,
    float* __restrict__ x)
{
    __shared__ float qs[TM * FDIM];
    __shared__ float hs[TM * FDIM];
    const int tid = threadIdx.x;
    const int atom0 = blockIdx.x * TM;

    for (int c = tid; c < TM * FDIM; c += 128)
        qs[c] = q[atom0 * FDIM + c];
    __syncthreads();

    const int f = tid;
    // h = silu(q @ W1 + b1)
    {
        float b1f = b1[f];
        float acc[TM];
#pragma unroll
        for (int a = 0; a < TM; a++) acc[a] = b1f;
#pragma unroll 4
        for (int k = 0; k < FDIM; k++) {
            float w = W1[k * FDIM + f];
#pragma unroll
            for (int a = 0; a < TM; a++) acc[a] += qs[a * FDIM + k] * w;
        }
#pragma unroll
        for (int a = 0; a < TM; a++) hs[a * FDIM + f] = silu(acc[a]);
    }
    __syncthreads();
    // x = h @ W2 + b2   (384 outputs; thread f does n = f, f+128, f+256)
    {
        float accA[TM], accB[TM], accC[TM];
        float bA = b2[f], bB = b2[FDIM + f], bC = b2[2 * FDIM + f];
#pragma unroll
        for (int a = 0; a < TM; a++) { accA[a] = bA; accB[a] = bB; accC[a] = bC; }
#pragma unroll 4
        for (int k = 0; k < FDIM; k++) {
            float w0 = W2[k * 384 + f];
            float w1 = W2[k * 384 + FDIM + f];
            float w2 = W2[k * 384 + 2 * FDIM + f];
#pragma unroll
            for (int a = 0; a < TM; a++) {
                float h = hs[a * FDIM + k];
                accA[a] += h * w0; accB[a] += h * w1; accC[a] += h * w2;
            }
        }
#pragma unroll
        for (int a = 0; a < TM; a++) {
            x[(atom0 + a) * 384 + f]            = accA[a];
            x[(atom0 + a) * 384 + FDIM + f]     = accB[a];
            x[(atom0 + a) * 384 + 2 * FDIM + f] = accC[a];
        }
    }
}

// ---------------------------------------------------------------------------
// Kernel 2: pair messages. One warp per pair, lane handles 4 features.
// W_ij computed on the fly from rbf and the block's filter slice (smem).
// Scatter via vectorized red.global.add.v4.f32 into g_dq / g_dmu.
// ---------------------------------------------------------------------------
__global__ void __launch_bounds__(128) k_pairs(
    const float* __restrict__ x, const float* __restrict__ mu,
    const float* __restrict__ dist, const float* __restrict__ vec,
    const float* __restrict__ cut, const float* __restrict__ rbf,
    const float* __restrict__ fW,   // pre-offset by b*384, row stride 1920
    const float* __restrict__ fb,   // pre-offset by b*384
    const int* __restrict__ idx_i, const int* __restrict__ idx_j,
    float* __restrict__ dq, float* __restrict__ dmu)
{
    __shared__ __align__(16) float fw_s[RD * 384];
    __shared__ __align__(16) float fb_s[384];
    const int tid = threadIdx.x;
    for (int c = tid; c < RD * 384; c += 128) {
        int r = c / 384, cc = c - r * 384;
        fw_s[c] = fW[r * 1920 + cc];
    }
    for (int c = tid; c < 384; c += 128) fb_s[c] = fb[c];
    __syncthreads();

    const int lane = tid & 31;
    const int gw = blockIdx.x * 4 + (tid >> 5);
    const int nw = gridDim.x * 4;
    const float4* fw4 = (const float4*)fw_s;   // [RD][96]
    const float4* fb4 = (const float4*)fb_s;   // [96]
    const float4* X4 = (const float4*)x;       // [NA][96]
    const float4* M4 = (const float4*)mu;      // [NA*3][32]

    for (int p = gw; p < NP; p += nw) {
        const int i = idx_i[p];
        const int j = idx_j[p];
        const float dinv = 1.f / dist[p];
        const float cu = cut[p];
        const float d0 = vec[3 * p] * dinv;
        const float d1 = vec[3 * p + 1] * dinv;
        const float d2 = vec[3 * p + 2] * dinv;

        float4 wq = make_float4(0.f, 0.f, 0.f, 0.f);
        float4 wr = wq, wm = wq;
#pragma unroll
        for (int r = 0; r < RD; r++) {
            float rb = rbf[p * RD + r];
            float4 t;
            t = fw4[r * 96 + lane];
            wq.x += rb * t.x; wq.y += rb * t.y; wq.z += rb * t.z; wq.w += rb * t.w;
            t = fw4[r * 96 + 32 + lane];
            wr.x += rb * t.x; wr.y += rb * t.y; wr.z += rb * t.z; wr.w += rb * t.w;
            t = fw4[r * 96 + 64 + lane];
            wm.x += rb * t.x; wm.y += rb * t.y; wm.z += rb * t.z; wm.w += rb * t.w;
        }
        {
            float4 t = fb4[lane];
            wq.x = (wq.x + t.x) * cu; wq.y = (wq.y + t.y) * cu;
            wq.z = (wq.z + t.z) * cu; wq.w = (wq.w + t.w) * cu;
            t = fb4[32 + lane];
            wr.x = (wr.x + t.x) * cu; wr.y = (wr.y + t.y) * cu;
            wr.z = (wr.z + t.z) * cu; wr.w = (wr.w + t.w) * cu;
            t = fb4[64 + lane];
            wm.x = (wm.x + t.x) * cu; wm.y = (wm.y + t.y) * cu;
            wm.z = (wm.z + t.z) * cu; wm.w = (wm.w + t.w) * cu;
        }
        const float4 xq = X4[j * 96 + lane];
        const float4 xr = X4[j * 96 + 32 + lane];
        const float4 xm = X4[j * 96 + 64 + lane];

        red4(dq + i * FDIM + lane * 4,
             xq.x * wq.x, xq.y * wq.y, xq.z * wq.z, xq.w * wq.w);

        const float ax = xr.x * wr.x, ay = xr.y * wr.y, az = xr.z * wr.z, aw = xr.w * wr.w;
        const float cx = xm.x * wm.x, cy = xm.y * wm.y, cz = xm.z * wm.z, cw = xm.w * wm.w;
#pragma unroll
        for (int d = 0; d < 3; d++) {
            const float dd = (d == 0) ? d0 : ((d == 1) ? d1 : d2);
            const float4 mj = M4[(j * 3 + d) * 32 + lane];
            red4(dmu + (i * 3 + d) * FDIM + lane * 4,
                 ax * dd + cx * mj.x,
                 ay * dd + cy * mj.y,
                 az * dd + cz * mj.z,
                 aw * dd + cw * mj.w);
        }
    }
}

// ---------------------------------------------------------------------------
// Kernel 3: fold in deltas, then mixing block (mu@Wv, vector norm, MLP,
// gated updates). TM atoms per CTA, dynamic smem.
// ---------------------------------------------------------------------------
__global__ void __launch_bounds__(128) k_mix(
    float* __restrict__ q, float* __restrict__ mu,
    const float* __restrict__ dq, const float* __restrict__ dmu,
    const float* __restrict__ Wv,                       // [128][256]
    const float* __restrict__ mW1, const float* __restrict__ mb1,  // [256][128],[128]
    const float* __restrict__ mW2, const float* __restrict__ mb2)  // [128][384],[384]
{
    extern __shared__ float sm[];
    float* qs  = sm;                  // TM*128
    float* mus = qs + TM * 128;       // TM*384
    float* mvs = mus + TM * 384;      // TM*384 (mu_V)
    float* mws = mvs + TM * 384;      // TM*384 (mu_W)
    float* ctxs = mws + TM * 384;     // TM*256
    float* hs  = ctxs + TM * 256;     // TM*128

    const int tid = threadIdx.x;
    const int atom0 = blockIdx.x * TM;
    const int f = tid;

    // 1. fold segment sums
    for (int c = tid; c < TM * FDIM; c += 128)
        qs[c] = q[atom0 * FDIM + c] + dq[atom0 * FDIM + c];
    for (int c = tid; c < TM * 384; c += 128)
        mus[c] = mu[atom0 * 384 + c] + dmu[atom0 * 384 + c];
    __syncthreads();

    // 2. [mu_V | mu_W] = mu @ Wv
    for (int d = 0; d < 3; d++) {
        float accV[TM], accW[TM];
#pragma unroll
        for (int a = 0; a < TM; a++) { accV[a] = 0.f; accW[a] = 0.f; }
#pragma unroll 4
        for (int k = 0; k < FDIM; k++) {
            float wv = Wv[k * 256 + f];
            float ww = Wv[k * 256 + FDIM + f];
#pragma unroll
            for (int a = 0; a < TM; a++) {
                float m = mus[a * 384 + d * FDIM + k];
                accV[a] += m * wv; accW[a] += m * ww;
            }
        }
#pragma unroll
        for (int a = 0; a < TM; a++) {
            mvs[a * 384 + d * FDIM + f] = accV[a];
            mws[a * 384 + d * FDIM + f] = accW[a];
        }
    }
    __syncthreads();

    // 3. ctx = [q, ||mu_V||]
#pragma unroll
    for (int a = 0; a < TM; a++) {
        ctxs[a * 256 + f] = qs[a * FDIM + f];
        float v0 = mvs[a * 384 + f];
        float v1 = mvs[a * 384 + FDIM + f];
        float v2 = mvs[a * 384 + 2 * FDIM + f];
        ctxs[a * 256 + FDIM + f] = sqrtf(v0 * v0 + v1 * v1 + v2 * v2 + 1e-8f);
    }
    __syncthreads();

    // 4. h = silu(ctx @ mW1 + mb1)
    {
        float b1f = mb1[f];
        float acc[TM];
#pragma unroll
        for (int a = 0; a < TM; a++) acc[a] = b1f;
#pragma unroll 4
        for (int k = 0; k < 256; k++) {
            float w = mW1[k * FDIM + f];
#pragma unroll
            for (int a = 0; a < TM; a++) acc[a] += ctxs[a * 256 + k] * w;
        }
#pragma unroll
        for (int a = 0; a < TM; a++) hs[a * FDIM + f] = silu(acc[a]);
    }
    __syncthreads();

    // 5. y = h @ mW2 + mb2 ; 6. gated update
    {
        float accA[TM], accB[TM], accC[TM];
        float bA = mb2[f], bB = mb2[FDIM + f], bC = mb2[2 * FDIM + f];
#pragma unroll
        for (int a = 0; a < TM; a++) { accA[a] = bA; accB[a] = bB; accC[a] = bC; }
#pragma unroll 4
        for (int k = 0; k < FDIM; k++) {
            float w0 = mW2[k * 384 + f];
            float w1 = mW2[k * 384 + FDIM + f];
            float w2 = mW2[k * 384 + 2 * FDIM + f];
#pragma unroll
            for (int a = 0; a < TM; a++) {
                float h = hs[a * FDIM + k];
                accA[a] += h * w0; accB[a] += h * w1; accC[a] += h * w2;
            }
        }
#pragma unroll
        for (int a = 0; a < TM; a++) {
            float dot = 0.f;
#pragma unroll
            for (int d = 0; d < 3; d++)
                dot += mvs[a * 384 + d * FDIM + f] * mws[a * 384 + d * FDIM + f];
            q[(atom0 + a) * FDIM + f] = qs[a * FDIM + f] + accA[a] + accC[a] * dot;
#pragma unroll
            for (int d = 0; d < 3; d++)
                mu[(atom0 + a) * 384 + d * FDIM + f] =
                    mus[a * 384 + d * FDIM + f] + accB[a] * mws[a * 384 + d * FDIM + f];
        }
    }
}

// ---------------------------------------------------------------------------
extern "C" void kernel_launch(void* const* d_in, const int* in_sizes, int n_in,
                              void* d_out, int out_size)
{
    const float* features = (const float*)d_in[0];
    const float* distances = (const float*)d_in[1];
    const float* vectors = (const float*)d_in[2];
    const float* cutoffs = (const float*)d_in[3];
    const float* rbfs = (const float*)d_in[4];
    const float* filter_W = (const float*)d_in[5];
    const float* filter_b = (const float*)d_in[6];
    const float* int_W1 = (const float*)d_in[7];
    const float* int_b1 = (const float*)d_in[8];
    const float* int_W2 = (const float*)d_in[9];
    const float* int_b2 = (const float*)d_in[10];
    const float* mix_Wv = (const float*)d_in[11];
    const float* mix_W1 = (const float*)d_in[12];
    const float* mix_b1 = (const float*)d_in[13];
    const float* mix_W2 = (const float*)d_in[14];
    const float* mix_b2 = (const float*)d_in[15];
    const int* idx_i = (const int*)d_in[16];
    const int* idx_j = (const int*)d_in[17];

    float* q = (float*)d_out;            // [NA,128]
    float* mu = q + NA * FDIM;           // [NA,3,128]

    float *xbuf, *dqbuf, *dmubuf;
    cudaGetSymbolAddress((void**)&xbuf, g_x);
    cudaGetSymbolAddress((void**)&dqbuf, g_dq);
    cudaGetSymbolAddress((void**)&dmubuf, g_dmu);

    const int smem_mix = (TM * 128 + TM * 384 * 3 + TM * 256 + TM * 128) * 4; // 106496 B
    cudaFuncSetAttribute(k_mix, cudaFuncAttributeMaxDynamicSharedMemorySize, smem_mix);

    cudaMemcpyAsync(q, features, NA * FDIM * sizeof(float), cudaMemcpyDeviceToDevice);
    cudaMemsetAsync(mu, 0, NA * 384 * sizeof(float));

    for (int b = 0; b < NB; b++) {
        k_x<<<NA / TM, 128>>>(q,
                              int_W1 + b * FDIM * FDIM, int_b1 + b * FDIM,
                              int_W2 + b * FDIM * 384, int_b2 + b * 384,
                              xbuf);
        cudaMemsetAsync(dqbuf, 0, NA * FDIM * sizeof(float));
        cudaMemsetAsync(dmubuf, 0, NA * 384 * sizeof(float));
        k_pairs<<<512, 128>>>(xbuf, mu, distances, vectors, cutoffs, rbfs,
                              filter_W + b * 384, filter_b + b * 384,
                              idx_i, idx_j, dqbuf, dmubuf);
        k_mix<<<NA / TM, 128, smem_mix>>>(q, mu, dqbuf, dmubuf,
                                          mix_Wv + b * FDIM * 256,
                                          mix_W1 + b * 256 * FDIM, mix_b1 + b * FDIM,
                                          mix_W2 + b * FDIM * 384, mix_b2 + b * 384);
    }
}